// round 8
// baseline (speedup 1.0000x reference)
#include <cuda_runtime.h>

#define HID   64
#define BATCH 16
#define SEQ   512
#define VOCAB 32000
#define NTOK  (BATCH * SEQ * 2)     // 16384
#define RPB   8                     // rows per rowvec block
#define IPB   128                   // worklist entries per accum block

// Scratch (no allocs allowed). Counters re-zeroed every launch.
__device__ int   g_cnt_vb[VOCAB * BATCH];   // count[v][b], 2 MB
__device__ int   g_cnt_v[VOCAB];            // dedup flag
__device__ int   g_rowlist[NTOK];           // distinct rows
__device__ int   g_nrows[1];
__device__ float g_rowvec[NTOK * HID];      // r_v = sos . E_v  (4 MB)
__device__ float g_acc[BATCH * HID];        // per-batch hidden

// ---------------------------------------------------------------- zero
__global__ __launch_bounds__(256) void zero_kernel() {
    const int i = blockIdx.x * 256 + threadIdx.x;
    const int4 z = make_int4(0, 0, 0, 0);
    if (i < VOCAB * BATCH / 4) reinterpret_cast<int4*>(g_cnt_vb)[i] = z;
    if (i < VOCAB / 4)         reinterpret_cast<int4*>(g_cnt_v)[i]  = z;
    if (i < BATCH * HID / 4)   reinterpret_cast<float4*>(g_acc)[i] =
                                   make_float4(0.f, 0.f, 0.f, 0.f);
    if (i == 0) g_nrows[0] = 0;
}

// ---------------------------------------------------------------- histogram
__global__ __launch_bounds__(256) void hist_kernel(
    const int* __restrict__ s1, const int* __restrict__ s2)
{
    const int t = blockIdx.x * 256 + threadIdx.x;    // 0..16383
    const int b = t >> 10;
    const int l = t & 1023;
    const int v = (l < SEQ) ? s1[b * SEQ + l] : s2[b * SEQ + (l - SEQ)];
    atomicAdd(&g_cnt_vb[v * BATCH + b], 1);
    if (atomicAdd(&g_cnt_v[v], 1) == 0) {
        const int pos = atomicAdd(&g_nrows[0], 1);
        g_rowlist[pos] = v;
    }
}

// ---------------------------------------------------------------- rowvec
// 8 distinct rows per 256-thread block: 32 independent float4 LDGs/thread
// before any sync (deep MLP), one block-end reduction, coalesced stores.
// Thread tid, float4 f = tid+256j: h-group = tid&15, w = (tid>>4)+16j.
__global__ __launch_bounds__(256) void rowvec_kernel(
    const float* __restrict__ embed,
    const float* __restrict__ sos)
{
    __shared__ float  s_sos[HID];
    __shared__ int    s_row[RPB];
    __shared__ int    s_nr;
    __shared__ float4 s_part[RPB * 256];     // 32 KB

    const int tid  = threadIdx.x;
    const int base = blockIdx.x * RPB;

    if (tid == 0) {
        int c = g_nrows[0] - base;
        s_nr = c < 0 ? 0 : (c > RPB ? RPB : c);
    }
    if (tid < HID) s_sos[tid] = sos[tid];
    if (tid < RPB) s_row[tid] = g_rowlist[base + tid];   // stale beyond nr unused
    __syncthreads();

    const int nr = s_nr;
    if (nr == 0) return;

    const int   wb = tid >> 4;
    const float s0 = s_sos[wb];
    const float sA = s_sos[wb + 16];
    const float sB = s_sos[wb + 32];
    const float sC = s_sos[wb + 48];

    #pragma unroll
    for (int r = 0; r < RPB; r++) {
        float4 acc = make_float4(0.f, 0.f, 0.f, 0.f);
        if (r < nr) {
            const float4* row = reinterpret_cast<const float4*>(embed)
                                + ((long long)s_row[r] << 10);
            const float4 v0 = __ldg(&row[tid      ]);
            const float4 v1 = __ldg(&row[tid + 256]);
            const float4 v2 = __ldg(&row[tid + 512]);
            const float4 v3 = __ldg(&row[tid + 768]);
            acc.x = s0 * v0.x;             acc.y = s0 * v0.y;
            acc.z = s0 * v0.z;             acc.w = s0 * v0.w;
            acc.x = fmaf(sA, v1.x, acc.x); acc.y = fmaf(sA, v1.y, acc.y);
            acc.z = fmaf(sA, v1.z, acc.z); acc.w = fmaf(sA, v1.w, acc.w);
            acc.x = fmaf(sB, v2.x, acc.x); acc.y = fmaf(sB, v2.y, acc.y);
            acc.z = fmaf(sB, v2.z, acc.z); acc.w = fmaf(sB, v2.w, acc.w);
            acc.x = fmaf(sC, v3.x, acc.x); acc.y = fmaf(sC, v3.y, acc.y);
            acc.z = fmaf(sC, v3.z, acc.z); acc.w = fmaf(sC, v3.w, acc.w);
        }
        s_part[r * 256 + tid] = acc;
    }
    __syncthreads();

    // 128 threads: thread (r = t>>4, hg = t&15) sums 16 w-partials, stores.
    if (tid < RPB * 16) {
        const int r  = tid >> 4;
        const int hg = tid & 15;
        if (r < nr) {
            float4 sum = make_float4(0.f, 0.f, 0.f, 0.f);
            #pragma unroll
            for (int j = 0; j < 16; j++) {
                const float4 p = s_part[r * 256 + hg + (j << 4)];
                sum.x += p.x; sum.y += p.y; sum.z += p.z; sum.w += p.w;
            }
            reinterpret_cast<float4*>(&g_rowvec[(base + r) * HID])[hg] = sum;
        }
    }
}

// ---------------------------------------------------------------- accum
// h[b] += cnt[v][b] * r_v over a chunk of the worklist.
// 256 threads = 16 batches x 16 h-groups; register float4 accumulator;
// one set of atomics per block at the end (~100 per address total).
__global__ __launch_bounds__(256) void accum_kernel()
{
    const int tid  = threadIdx.x;
    const int bb   = tid >> 4;    // batch
    const int hg   = tid & 15;    // h-group
    const int base = blockIdx.x * IPB;

    const int n   = g_nrows[0];
    int       end = n - base;
    if (end <= 0) return;
    if (end > IPB) end = IPB;

    float4 acc = make_float4(0.f, 0.f, 0.f, 0.f);
    #pragma unroll 4
    for (int i = 0; i < end; i++) {
        const int idx = base + i;
        const int v   = g_rowlist[idx];
        const int c   = g_cnt_vb[v * BATCH + bb];
        if (c) {
            const float  f  = (float)c;
            const float4 rv = reinterpret_cast<const float4*>(
                                  &g_rowvec[idx * HID])[hg];
            acc.x = fmaf(f, rv.x, acc.x); acc.y = fmaf(f, rv.y, acc.y);
            acc.z = fmaf(f, rv.z, acc.z); acc.w = fmaf(f, rv.w, acc.w);
        }
    }
    float* dst = &g_acc[bb * HID + (hg << 2)];
    atomicAdd(dst + 0, acc.x);
    atomicAdd(dst + 1, acc.y);
    atomicAdd(dst + 2, acc.z);
    atomicAdd(dst + 3, acc.w);
}

// ---------------------------------------------------------------- MLP
#define W1T_STRIDE 65
__global__ __launch_bounds__(256) void mlp_kernel(
    const float* __restrict__ w1,
    const float* __restrict__ b1,
    const float* __restrict__ w2,
    const float* __restrict__ b2,
    float*       __restrict__ out)
{
    __shared__ float w1t[HID * W1T_STRIDE];
    __shared__ float sh[HID];
    __shared__ float sx[HID];

    const int b   = blockIdx.x;
    const int tid = threadIdx.x;

    #pragma unroll
    for (int j = 0; j < 16; j++) {
        const int idx = tid + 256 * j;            // 0..4095
        w1t[(idx & 63) * W1T_STRIDE + (idx >> 6)] = w1[idx];
    }
    if (tid < HID) sh[tid] = g_acc[b * HID + tid];
    __syncthreads();

    if (tid < HID) {
        float sum = b1[tid];
        #pragma unroll
        for (int k = 0; k < HID; k++)
            sum = fmaf(sh[k], w1t[k * W1T_STRIDE + tid], sum);
        sx[tid] = fmaxf(sum, 0.0f);
    }
    __syncthreads();

    if (tid < 2) {
        float s2 = b2[tid];
        #pragma unroll
        for (int k = 0; k < HID; k++)
            s2 = fmaf(sx[k], w2[tid * HID + k], s2);
        out[b * 2 + tid] = s2;
    }
}

extern "C" void kernel_launch(void* const* d_in, const int* in_sizes, int n_in,
                              void* d_out, int out_size)
{
    const int*   s1    = (const int*)  d_in[0];
    const int*   s2    = (const int*)  d_in[1];
    const float* embed = (const float*)d_in[2];
    const float* sos   = (const float*)d_in[3];
    const float* w1    = (const float*)d_in[4];
    const float* b1    = (const float*)d_in[5];
    const float* w2    = (const float*)d_in[6];
    const float* b2    = (const float*)d_in[7];
    float* out = (float*)d_out;

    zero_kernel<<<(VOCAB * BATCH / 4 + 255) / 256, 256>>>();
    hist_kernel<<<NTOK / 256, 256>>>(s1, s2);
    rowvec_kernel<<<NTOK / RPB, 256>>>(embed, sos);
    accum_kernel<<<NTOK / IPB, 256>>>();
    mlp_kernel<<<BATCH, 256>>>(w1, b1, w2, b2, out);
}

// round 9
// speedup vs baseline: 1.6420x; 1.6420x over previous
#include <cuda_runtime.h>

#define HID   64
#define BATCH 16
#define SEQ   512
#define VOCAB 32000
#define NTOK  (BATCH * SEQ * 2)     // 16384
#define RPB   8                     // rows per rowvec block
#define NRVB  (NTOK / RPB)          // 2048 rowvec blocks (capacity = all distinct)

// Scratch (no device allocs allowed).
__device__ int   g_cnt_v[VOCAB];            // dedup flag/count (zeroed each launch)
__device__ int   g_slot[VOCAB];             // v -> worklist index (written at first touch)
__device__ int   g_rowlist[NTOK];           // distinct rows; pad entries pre-filled 0
__device__ int   g_nrows[1];
__device__ float g_rowvec[NTOK * HID];      // r_v = sos . E_v   (4 MB)
__device__ float g_part2[BATCH * 4 * HID];  // per-(batch,chunk) partials (16 KB)

// ---------------------------------------------------------------- zero
// Clears cnt_v + nrows and pre-fills rowlist with 0 (PAD row -> zeros), so
// rowvec can run branch-free per-row. ~200 KB of stores.
__global__ __launch_bounds__(256) void zero_kernel() {
    const int i = blockIdx.x * 256 + threadIdx.x;
    const int4 z = make_int4(0, 0, 0, 0);
    if (i < VOCAB / 4) reinterpret_cast<int4*>(g_cnt_v)[i]   = z;
    if (i < NTOK / 4)  reinterpret_cast<int4*>(g_rowlist)[i] = z;
    if (i == 0) g_nrows[0] = 0;
}

// ---------------------------------------------------------------- histogram
// First toucher of row v claims a worklist slot and records v -> slot.
__global__ __launch_bounds__(256) void hist_kernel(
    const int* __restrict__ s1, const int* __restrict__ s2)
{
    const int t = blockIdx.x * 256 + threadIdx.x;    // 0..16383
    const int b = t >> 10;
    const int l = t & 1023;
    const int v = (l < SEQ) ? s1[b * SEQ + l] : s2[b * SEQ + (l - SEQ)];
    if (atomicAdd(&g_cnt_v[v], 1) == 0) {
        const int pos = atomicAdd(&g_nrows[0], 1);
        g_rowlist[pos] = v;
        g_slot[v] = pos;
    }
}

// ---------------------------------------------------------------- rowvec
// 8 distinct rows per 256-thread block, BRANCH-FREE inner loop (pad rows are
// row 0): 32 independent float4 LDGs per thread before any sync.
// Thread tid, float4 f = tid+256j: h-group = tid&15, w = (tid>>4)+16j.
__global__ __launch_bounds__(256) void rowvec_kernel(
    const float* __restrict__ embed,
    const float* __restrict__ sos)
{
    __shared__ float  s_sos[HID];
    __shared__ int    s_row[RPB];
    __shared__ float4 s_part[RPB * 256];     // 32 KB

    const int tid  = threadIdx.x;
    const int base = blockIdx.x * RPB;

    if (base >= g_nrows[0]) return;          // block-level early exit only

    if (tid < HID) s_sos[tid] = sos[tid];
    if (tid < RPB) s_row[tid] = g_rowlist[base + tid];
    __syncthreads();

    const int   wb = tid >> 4;
    const float s0 = s_sos[wb];
    const float sA = s_sos[wb + 16];
    const float sB = s_sos[wb + 32];
    const float sC = s_sos[wb + 48];

    #pragma unroll
    for (int r = 0; r < RPB; r++) {
        const float4* row = reinterpret_cast<const float4*>(embed)
                            + ((long long)s_row[r] << 10);
        const float4 v0 = __ldg(&row[tid      ]);
        const float4 v1 = __ldg(&row[tid + 256]);
        const float4 v2 = __ldg(&row[tid + 512]);
        const float4 v3 = __ldg(&row[tid + 768]);
        float4 acc;
        acc.x = s0 * v0.x;             acc.y = s0 * v0.y;
        acc.z = s0 * v0.z;             acc.w = s0 * v0.w;
        acc.x = fmaf(sA, v1.x, acc.x); acc.y = fmaf(sA, v1.y, acc.y);
        acc.z = fmaf(sA, v1.z, acc.z); acc.w = fmaf(sA, v1.w, acc.w);
        acc.x = fmaf(sB, v2.x, acc.x); acc.y = fmaf(sB, v2.y, acc.y);
        acc.z = fmaf(sB, v2.z, acc.z); acc.w = fmaf(sB, v2.w, acc.w);
        acc.x = fmaf(sC, v3.x, acc.x); acc.y = fmaf(sC, v3.y, acc.y);
        acc.z = fmaf(sC, v3.z, acc.z); acc.w = fmaf(sC, v3.w, acc.w);
        s_part[r * 256 + tid] = acc;
    }
    __syncthreads();

    // 128 threads: (r = t>>4, hg = t&15) sum 16 w-partials, coalesced store.
    if (tid < RPB * 16) {
        const int r  = tid >> 4;
        const int hg = tid & 15;
        float4 sum = make_float4(0.f, 0.f, 0.f, 0.f);
        #pragma unroll
        for (int j = 0; j < 16; j++) {
            const float4 p = s_part[r * 256 + hg + (j << 4)];
            sum.x += p.x; sum.y += p.y; sum.z += p.z; sum.w += p.w;
        }
        reinterpret_cast<float4*>(&g_rowvec[(base + r) * HID])[hg] = sum;
    }
}

// ---------------------------------------------------------------- accum
// Token-based, atomic-free, deterministic. 64 blocks = 16 batches x 4 chunks
// of 256 tokens. Phase 1: stage token->slot in shared (independent scattered
// loads). Phase 2: 16 independent float4 loads/thread from L2-resident
// g_rowvec. Block-reduce, plain store to g_part2.
__global__ __launch_bounds__(256) void accum_kernel(
    const int* __restrict__ s1, const int* __restrict__ s2)
{
    __shared__ int    s_slot[256];
    __shared__ float4 s_red[256];

    const int tid   = threadIdx.x;
    const int b     = blockIdx.x >> 2;
    const int chunk = blockIdx.x & 3;

    // Phase 1: token -> slot
    {
        const int l = chunk * 256 + tid;          // 0..1023
        const int v = (l < SEQ) ? s1[b * SEQ + l]
                                : s2[b * SEQ + (l - SEQ)];
        s_slot[tid] = g_slot[v];
    }
    __syncthreads();

    // Phase 2: each thread (lane = tid>>4 token sub-group, hg = tid&15)
    const int lane = tid >> 4;
    const int hg   = tid & 15;
    const float4* rv = reinterpret_cast<const float4*>(g_rowvec);

    float4 acc = make_float4(0.f, 0.f, 0.f, 0.f);
    #pragma unroll
    for (int i = 0; i < 16; i++) {
        const int idx = s_slot[lane * 16 + i];
        const float4 p = __ldg(&rv[idx * 16 + hg]);
        acc.x += p.x; acc.y += p.y; acc.z += p.z; acc.w += p.w;
    }
    s_red[tid] = acc;
    __syncthreads();

    // Reduce 16 lanes per hg, store partial (no atomics).
    if (tid < 16) {
        float4 sum = make_float4(0.f, 0.f, 0.f, 0.f);
        #pragma unroll
        for (int j = 0; j < 16; j++) {
            const float4 p = s_red[j * 16 + tid];
            sum.x += p.x; sum.y += p.y; sum.z += p.z; sum.w += p.w;
        }
        reinterpret_cast<float4*>(
            &g_part2[(b * 4 + chunk) * HID])[tid] = sum;
    }
}

// ---------------------------------------------------------------- MLP
// One block per batch; w1 staged transposed (pad-65, conflict-free).
#define W1T_STRIDE 65
__global__ __launch_bounds__(256) void mlp_kernel(
    const float* __restrict__ w1,
    const float* __restrict__ b1,
    const float* __restrict__ w2,
    const float* __restrict__ b2,
    float*       __restrict__ out)
{
    __shared__ float w1t[HID * W1T_STRIDE];
    __shared__ float sh[HID];
    __shared__ float sx[HID];

    const int b   = blockIdx.x;
    const int tid = threadIdx.x;

    #pragma unroll
    for (int j = 0; j < 16; j++) {
        const int idx = tid + 256 * j;            // 0..4095
        w1t[(idx & 63) * W1T_STRIDE + (idx >> 6)] = w1[idx];
    }
    if (tid < HID)
        sh[tid] = g_part2[(b * 4 + 0) * HID + tid]
                + g_part2[(b * 4 + 1) * HID + tid]
                + g_part2[(b * 4 + 2) * HID + tid]
                + g_part2[(b * 4 + 3) * HID + tid];
    __syncthreads();

    if (tid < HID) {
        float sum = b1[tid];
        #pragma unroll
        for (int k = 0; k < HID; k++)
            sum = fmaf(sh[k], w1t[k * W1T_STRIDE + tid], sum);
        sx[tid] = fmaxf(sum, 0.0f);
    }
    __syncthreads();

    if (tid < 2) {
        float s2 = b2[tid];
        #pragma unroll
        for (int k = 0; k < HID; k++)
            s2 = fmaf(sx[k], w2[tid * HID + k], s2);
        out[b * 2 + tid] = s2;
    }
}

extern "C" void kernel_launch(void* const* d_in, const int* in_sizes, int n_in,
                              void* d_out, int out_size)
{
    const int*   s1    = (const int*)  d_in[0];
    const int*   s2    = (const int*)  d_in[1];
    const float* embed = (const float*)d_in[2];
    const float* sos   = (const float*)d_in[3];
    const float* w1    = (const float*)d_in[4];
    const float* b1    = (const float*)d_in[5];
    const float* w2    = (const float*)d_in[6];
    const float* b2    = (const float*)d_in[7];
    float* out = (float*)d_out;

    zero_kernel<<<(VOCAB / 4 + 255) / 256, 256>>>();
    hist_kernel<<<NTOK / 256, 256>>>(s1, s2);
    rowvec_kernel<<<NRVB, 256>>>(embed, sos);
    accum_kernel<<<BATCH * 4, 256>>>(s1, s2);
    mlp_kernel<<<BATCH, 256>>>(w1, b1, w2, b2, out);
}

// round 10
// speedup vs baseline: 1.9110x; 1.1639x over previous
#include <cuda_runtime.h>

#define HID   64
#define BATCH 16
#define SEQ   512
#define VOCAB 32000
#define NTOK  (BATCH * SEQ * 2)     // 16384
#define RPB   8                     // rows per rowvec block (1 per warp)
#define NRVB  (NTOK / RPB)          // 2048
#define NCH   8                     // accum chunks per batch (128 tokens each)

// Scratch (no device allocs allowed).
__device__ int   g_cnt_v[VOCAB];              // dedup flag (zeroed each launch)
__device__ int   g_slot[VOCAB];               // v -> worklist slot
__device__ int   g_rowlist[NTOK];             // distinct rows; pad pre-filled 0
__device__ int   g_nrows[1];
__device__ float g_rowvec[NTOK * HID];        // r_v = sos . E_v  (4 MB)
__device__ float g_part2[BATCH * NCH * HID];  // per-(batch,chunk) partials

// ---------------------------------------------------------------- zero
__global__ __launch_bounds__(256) void zero_kernel() {
    const int i = blockIdx.x * 256 + threadIdx.x;
    const int4 z = make_int4(0, 0, 0, 0);
    if (i < VOCAB / 4) reinterpret_cast<int4*>(g_cnt_v)[i]   = z;
    if (i < NTOK / 4)  reinterpret_cast<int4*>(g_rowlist)[i] = z;
    if (i == 0) g_nrows[0] = 0;
}

// ---------------------------------------------------------------- histogram
__global__ __launch_bounds__(256) void hist_kernel(
    const int* __restrict__ s1, const int* __restrict__ s2)
{
    const int t = blockIdx.x * 256 + threadIdx.x;    // 0..16383
    const int b = t >> 10;
    const int l = t & 1023;
    const int v = (l < SEQ) ? s1[b * SEQ + l] : s2[b * SEQ + (l - SEQ)];
    if (atomicAdd(&g_cnt_v[v], 1) == 0) {
        const int pos = atomicAdd(&g_nrows[0], 1);
        g_rowlist[pos] = v;
        g_slot[v] = pos;
    }
}

// ---------------------------------------------------------------- rowvec
// WARP-PER-ROW: lane loads float4 f = lane + 32j (warp-load = 512B
// contiguous), accumulates into ONE register float4. hg = lane&15 fixed;
// w = (lane>>4) + 2j. No shared partials, no __syncthreads in hot path.
// shfl_xor(16) merges half-warps; 16 lanes store 256B coalesced.
__global__ __launch_bounds__(256) void rowvec_kernel(
    const float* __restrict__ embed,
    const float* __restrict__ sos)
{
    __shared__ float s_sos[HID];
    __shared__ int   s_row[RPB];

    const int tid  = threadIdx.x;
    const int base = blockIdx.x * RPB;

    if (base >= g_nrows[0]) return;          // block-level early exit

    if (tid < HID) s_sos[tid] = sos[tid];
    if (tid < RPB) s_row[tid] = g_rowlist[base + tid];  // pad rows = 0 (PAD)
    __syncthreads();

    const int wid  = tid >> 5;               // warp = row
    const int lane = tid & 31;
    const int wb   = lane >> 4;              // 0 or 1 (w parity)

    const float4* row = reinterpret_cast<const float4*>(embed)
                        + ((long long)s_row[wid] << 10);

    float4 acc = make_float4(0.f, 0.f, 0.f, 0.f);
    #pragma unroll 8
    for (int j = 0; j < 32; j++) {
        const float4 v = __ldg(&row[lane + (j << 5)]);
        const float  s = s_sos[wb + (j << 1)];
        acc.x = fmaf(s, v.x, acc.x); acc.y = fmaf(s, v.y, acc.y);
        acc.z = fmaf(s, v.z, acc.z); acc.w = fmaf(s, v.w, acc.w);
    }

    // Merge the two half-warps (lane l and l+16 share hg = l&15).
    acc.x += __shfl_xor_sync(0xffffffffu, acc.x, 16);
    acc.y += __shfl_xor_sync(0xffffffffu, acc.y, 16);
    acc.z += __shfl_xor_sync(0xffffffffu, acc.z, 16);
    acc.w += __shfl_xor_sync(0xffffffffu, acc.w, 16);

    if (lane < 16)
        reinterpret_cast<float4*>(&g_rowvec[(base + wid) * HID])[lane] = acc;
}

// ---------------------------------------------------------------- accum
// Token-based, atomic-free, deterministic. 128 blocks = 16 batches x 8
// chunks of 128 tokens. Phase 1: stage token->slot. Phase 2: thread
// (lane = tid>>4, hg = tid&15) sums 8 tokens' float4s from L2-resident
// g_rowvec. Block-reduce in shared, plain store.
__global__ __launch_bounds__(256) void accum_kernel(
    const int* __restrict__ s1, const int* __restrict__ s2)
{
    __shared__ int    s_slot[128];
    __shared__ float4 s_red[256];

    const int tid   = threadIdx.x;
    const int b     = blockIdx.x >> 3;
    const int chunk = blockIdx.x & 7;

    if (tid < 128) {
        const int l = chunk * 128 + tid;          // 0..1023
        const int v = (l < SEQ) ? s1[b * SEQ + l]
                                : s2[b * SEQ + (l - SEQ)];
        s_slot[tid] = g_slot[v];
    }
    __syncthreads();

    const int lane = tid >> 4;    // 0..15: token sub-group
    const int hg   = tid & 15;
    const float4* rv = reinterpret_cast<const float4*>(g_rowvec);

    float4 acc = make_float4(0.f, 0.f, 0.f, 0.f);
    #pragma unroll
    for (int i = 0; i < 8; i++) {
        const int idx = s_slot[lane * 8 + i];
        const float4 p = __ldg(&rv[idx * 16 + hg]);
        acc.x += p.x; acc.y += p.y; acc.z += p.z; acc.w += p.w;
    }
    s_red[tid] = acc;
    __syncthreads();

    if (tid < 16) {
        float4 sum = make_float4(0.f, 0.f, 0.f, 0.f);
        #pragma unroll
        for (int j = 0; j < 16; j++) {
            const float4 p = s_red[j * 16 + tid];
            sum.x += p.x; sum.y += p.y; sum.z += p.z; sum.w += p.w;
        }
        reinterpret_cast<float4*>(
            &g_part2[(b * NCH + chunk) * HID])[tid] = sum;
    }
}

// ---------------------------------------------------------------- MLP
// One block per batch; w1 staged transposed (pad-65, conflict-free).
#define W1T_STRIDE 65
__global__ __launch_bounds__(256) void mlp_kernel(
    const float* __restrict__ w1,
    const float* __restrict__ b1,
    const float* __restrict__ w2,
    const float* __restrict__ b2,
    float*       __restrict__ out)
{
    __shared__ float w1t[HID * W1T_STRIDE];
    __shared__ float sh[HID];
    __shared__ float sx[HID];

    const int b   = blockIdx.x;
    const int tid = threadIdx.x;

    #pragma unroll
    for (int j = 0; j < 16; j++) {
        const int idx = tid + 256 * j;            // 0..4095
        w1t[(idx & 63) * W1T_STRIDE + (idx >> 6)] = w1[idx];
    }
    if (tid < HID) {
        float s = 0.0f;
        #pragma unroll
        for (int c = 0; c < NCH; c++)
            s += g_part2[(b * NCH + c) * HID + tid];
        sh[tid] = s;
    }
    __syncthreads();

    if (tid < HID) {
        float sum = b1[tid];
        #pragma unroll
        for (int k = 0; k < HID; k++)
            sum = fmaf(sh[k], w1t[k * W1T_STRIDE + tid], sum);
        sx[tid] = fmaxf(sum, 0.0f);
    }
    __syncthreads();

    if (tid < 2) {
        float s2 = b2[tid];
        #pragma unroll
        for (int k = 0; k < HID; k++)
            s2 = fmaf(sx[k], w2[tid * HID + k], s2);
        out[b * 2 + tid] = s2;
    }
}

extern "C" void kernel_launch(void* const* d_in, const int* in_sizes, int n_in,
                              void* d_out, int out_size)
{
    const int*   s1    = (const int*)  d_in[0];
    const int*   s2    = (const int*)  d_in[1];
    const float* embed = (const float*)d_in[2];
    const float* sos   = (const float*)d_in[3];
    const float* w1    = (const float*)d_in[4];
    const float* b1    = (const float*)d_in[5];
    const float* w2    = (const float*)d_in[6];
    const float* b2    = (const float*)d_in[7];
    float* out = (float*)d_out;

    zero_kernel<<<(VOCAB / 4 + 255) / 256, 256>>>();
    hist_kernel<<<NTOK / 256, 256>>>(s1, s2);
    rowvec_kernel<<<NRVB, 256>>>(embed, sos);
    accum_kernel<<<BATCH * NCH, 256>>>(s1, s2);
    mlp_kernel<<<BATCH, 256>>>(w1, b1, w2, b2, out);
}